// round 9
// baseline (speedup 1.0000x reference)
#include <cuda_runtime.h>
#include <math.h>

#define T_STEPS 1024
#define NB 128
#define FD 128
#define HD 128
#define LA 8            // xpre production lookahead (steps)

typedef unsigned long long u64;

__device__ __forceinline__ u64 pack2(float lo, float hi) {
    u64 r;
    asm("mov.b64 %0, {%1, %2};" : "=l"(r) : "f"(lo), "f"(hi));
    return r;
}
__device__ __forceinline__ void unpack2(u64 v, float& lo, float& hi) {
    asm("mov.b64 {%0, %1}, %2;" : "=f"(lo), "=f"(hi) : "l"(v));
}
__device__ __forceinline__ u64 fma2(u64 a, u64 b, u64 c) {
    u64 r;
    asm("fma.rn.f32x2 %0, %1, %2, %3;" : "=l"(r) : "l"(a), "l"(b), "l"(c));
    return r;
}
__device__ __forceinline__ u64 add2(u64 a, u64 b) {
    u64 r;
    asm("add.rn.f32x2 %0, %1, %2;" : "=l"(r) : "l"(a), "l"(b));
    return r;
}
__device__ __forceinline__ float ex2f(float x) {
    float r;
    asm("ex2.approx.f32 %0, %1;" : "=f"(r) : "f"(x));
    return r;
}
__device__ __forceinline__ float rcpf(float x) {
    float r;
    asm("rcp.approx.f32 %0, %1;" : "=f"(r) : "f"(x));
    return r;
}

// ---------------------------------------------------------------------------
// Fully fused, software-pipelined kernel: ONE CTA per batch row (128 thr).
// xpre row t (8 floats: y-offsets [0:4), closed-form x-VQC [4:8)) is produced
// INSIDE the step loop by warp (t&3), LA steps ahead of consumption, with x
// data LDG-prefetched 4 production slots ahead. No separate phase, no global
// scratch. Phase-2 step structure = R5/R8 (proven): lane 8m+sub owns sums
// {2m,2m+1} over h[16sub..+16), 3-shuffle value-split reduction, one warp-wide
// MUFU.COS -> 12 gate cosines via per-warp smem slot, ex2-folded
// merged-division GRU update.
// ---------------------------------------------------------------------------
__global__ void __launch_bounds__(128, 1) qgru_fused(
    const float* __restrict__ x,
    const float* __restrict__ W_in, const float* __restrict__ b_in,
    const float* __restrict__ W_x,  const float* __restrict__ b_x,
    const float* __restrict__ W_h,  const float* __restrict__ b_h,
    const float* __restrict__ W_out, const float* __restrict__ b_out,
    const float* __restrict__ vqc_w,
    float* __restrict__ out)
{
    const int b    = blockIdx.x;
    const int j    = threadIdx.x;
    const int lane = j & 31;
    const int wid  = j >> 5;
    const int m    = lane >> 3;    // sum pair {2m, 2m+1}
    const int sub  = lane & 7;     // element slice [16*sub, 16*sub+16)

    __shared__ __align__(16) float xs[T_STEPS * 8];     // 32 KB xpre for row b
    __shared__ __align__(16) float h_sh[2][HD];
    __shared__ __align__(16) float cos_sh[4][16];       // slots 0..11 used

    const int k0 = 2 * m, k1 = 2 * m + 1;

    // ---- phase-2 dot weights (h-part): sums k0 (A), k1 (B) over h[16sub..)
    const float* r0 = (k0 < 4) ? (W_in + k0 * (HD + FD)) : (W_h + (k0 - 4) * HD);
    const float* r1 = (k1 < 4) ? (W_in + k1 * (HD + FD)) : (W_h + (k1 - 4) * HD);
    u64 wA[8], wB[8];
#pragma unroll
    for (int i = 0; i < 8; i++) {
        wA[i] = pack2(r0[sub * 16 + 2 * i], r0[sub * 16 + 2 * i + 1]);
        wB[i] = pack2(r1[sub * 16 + 2 * i], r1[sub * 16 + 2 * i + 1]);
    }

    // ---- production dot weights (x-part): same layout over x[16sub..)
    const float* rx0 = (k0 < 4) ? (W_in + k0 * (HD + FD) + HD)
                                : (W_x + (k0 - 4) * FD);
    const float* rx1 = (k1 < 4) ? (W_in + k1 * (HD + FD) + HD)
                                : (W_x + (k1 - 4) * FD);
    u64 pA[8], pB[8];
#pragma unroll
    for (int i = 0; i < 8; i++) {
        pA[i] = pack2(rx0[sub * 16 + 2 * i], rx0[sub * 16 + 2 * i + 1]);
        pB[i] = pack2(rx1[sub * 16 + 2 * i], rx1[sub * 16 + 2 * i + 1]);
    }

    // W_out prescaled: RZ by log2e (exp(-o)), HX by 2*log2e (exp(-2u))
    const float L2E = 1.4426950408889634f;
    float woRZ[4], woHX[4];
#pragma unroll
    for (int kk = 0; kk < 4; kk++) {
        float w = W_out[j * 4 + kk];
        woRZ[kk] = w * L2E;
        woHX[kk] = w * (2.0f * L2E);
    }
    const float bof  = b_out[j];
    const float boRZ = bof * L2E;
    const float boHX = bof * (2.0f * L2E);

    // ---- roles (loop-invariant). After the 3-shuffle split, lanes 8m+{0..3}
    // hold sum 2m, lanes 8m+{4..7} hold sum 2m+1.
    const int k_owned = 2 * m + ((sub >> 2) & 1);

    // phase-2 gate-cosine role
    int slot = -1;
    float cadd = 0.0f;
    if (m < 2) {
        if ((sub & 3) == 0)      { slot = k_owned;     cadd = vqc_w[k_owned]; }
        else if ((sub & 3) == 1) { slot = 4 + k_owned; cadd = vqc_w[4 + k_owned]; }
    } else {
        int kk = k_owned - 4;
        if ((sub & 3) == 0)      { slot = 8 + kk; cadd = vqc_w[12 + kk] + b_h[kk]; }
    }
    const bool use_p = (m < 2);
    const int  pidx  = k_owned & 3;

    // production role
    const float pbias = (k_owned < 4)
        ? b_in[k_owned]
        : (b_x[k_owned - 4] + vqc_w[8 + (k_owned - 4)]);   // + w2
    const bool pstore = ((sub & 3) == 0);

    const float* __restrict__ xrow = x + (size_t)b * T_STEPS * FD + 16 * sub;

    // ---- xpre production: dot over x[tp,16sub..+16), split-reduce, closed-form VQC
    auto produce = [&](int tp, float4 v0, float4 v1, float4 v2, float4 v3) {
        u64 x0 = pack2(v0.x, v0.y), x1 = pack2(v0.z, v0.w);
        u64 x2 = pack2(v1.x, v1.y), x3 = pack2(v1.z, v1.w);
        u64 x4 = pack2(v2.x, v2.y), x5 = pack2(v2.z, v2.w);
        u64 x6 = pack2(v3.x, v3.y), x7 = pack2(v3.z, v3.w);

        u64 aA0 = 0ull, aA1 = 0ull, aB0 = 0ull, aB1 = 0ull;
        aA0 = fma2(x0, pA[0], aA0); aA1 = fma2(x1, pA[1], aA1);
        aB0 = fma2(x0, pB[0], aB0); aB1 = fma2(x1, pB[1], aB1);
        aA0 = fma2(x2, pA[2], aA0); aA1 = fma2(x3, pA[3], aA1);
        aB0 = fma2(x2, pB[2], aB0); aB1 = fma2(x3, pB[3], aB1);
        aA0 = fma2(x4, pA[4], aA0); aA1 = fma2(x5, pA[5], aA1);
        aB0 = fma2(x4, pB[4], aB0); aB1 = fma2(x5, pB[5], aB1);
        aA0 = fma2(x6, pA[6], aA0); aA1 = fma2(x7, pA[7], aA1);
        aB0 = fma2(x6, pB[6], aB0); aB1 = fma2(x7, pB[7], aB1);

        aA0 = add2(aA0, aA1);
        aB0 = add2(aB0, aB1);
        float alo, ahi, blo, bhi;
        unpack2(aA0, alo, ahi);
        unpack2(aB0, blo, bhi);
        float sA = alo + ahi;
        float sB = blo + bhi;

        float send = (sub & 4) ? sA : sB;
        float recv = __shfl_xor_sync(0xffffffffu, send, 4);
        float s = ((sub & 4) ? sB : sA) + recv;
        s += __shfl_xor_sync(0xffffffffu, s, 2);
        s += __shfl_xor_sync(0xffffffffu, s, 1);

        float val = s + pbias;
        float cv  = __cosf(val);               // meaningful for k_owned>=4
        float c0 = __shfl_sync(0xffffffffu, cv, 16);
        float c1 = __shfl_sync(0xffffffffu, cv, 20);
        float c2 = __shfl_sync(0xffffffffu, cv, 24);
        float c3 = __shfl_sync(0xffffffffu, cv, 28);

        if (pstore) {
            float sval;
            if (k_owned < 4) {
                sval = val;                     // y-offset component
            } else {
                float z1 = c0 * c1, z2 = z1 * c2;
                sval = (k_owned == 4) ? c1 * c2 * c3
                     : (k_owned == 5) ? z1
                     : (k_owned == 6) ? z2
                                      : z2 * c3;
            }
            xs[tp * 8 + k_owned] = sval;
        }
    };

    // ---- prologue: each warp produces rows wid and wid+4; prefetch wid+8
    {
        float4 a0 = *reinterpret_cast<const float4*>(xrow + (size_t)wid * FD + 0);
        float4 a1 = *reinterpret_cast<const float4*>(xrow + (size_t)wid * FD + 4);
        float4 a2 = *reinterpret_cast<const float4*>(xrow + (size_t)wid * FD + 8);
        float4 a3 = *reinterpret_cast<const float4*>(xrow + (size_t)wid * FD + 12);
        float4 b0 = *reinterpret_cast<const float4*>(xrow + (size_t)(wid + 4) * FD + 0);
        float4 b1 = *reinterpret_cast<const float4*>(xrow + (size_t)(wid + 4) * FD + 4);
        float4 b2 = *reinterpret_cast<const float4*>(xrow + (size_t)(wid + 4) * FD + 8);
        float4 b3 = *reinterpret_cast<const float4*>(xrow + (size_t)(wid + 4) * FD + 12);
        produce(wid,     a0, a1, a2, a3);
        produce(wid + 4, b0, b1, b2, b3);
    }
    float4 xn0 = *reinterpret_cast<const float4*>(xrow + (size_t)(wid + 8) * FD + 0);
    float4 xn1 = *reinterpret_cast<const float4*>(xrow + (size_t)(wid + 8) * FD + 4);
    float4 xn2 = *reinterpret_cast<const float4*>(xrow + (size_t)(wid + 8) * FD + 8);
    float4 xn3 = *reinterpret_cast<const float4*>(xrow + (size_t)(wid + 8) * FD + 12);

    float hj = 0.0f;
    h_sh[0][j] = 0.0f;

    // c_last = zeros
    out[(size_t)NB * T_STEPS * HD + (size_t)NB * HD + b * HD + j] = 0.0f;

    float* __restrict__ orow = out + (size_t)b * T_STEPS * HD + j;
    float* cbuf = cos_sh[wid];

    __syncthreads();   // xs[0..LA) + h_sh[0] ready

    float prev = 0.0f;

#pragma unroll 1
    for (int t = 0; t < T_STEPS; t++) {
        // h reads first: 4 LDS.128 per lane
        const ulonglong2* hp = reinterpret_cast<const ulonglong2*>(
            h_sh[t & 1] + sub * 16);
        ulonglong2 q0 = hp[0];
        ulonglong2 q1 = hp[1];
        ulonglong2 q2 = hp[2];
        ulonglong2 q3 = hp[3];

        // previous step's hidden-seq store, off the pre-barrier path
        if (t) orow[(size_t)(t - 1) * HD] = prev;

        // ---- rotating xpre production (one warp per step, LA ahead)
        const int tp = t + LA;
        if (tp < T_STEPS && (tp & 3) == wid) {
            float4 v0 = xn0, v1 = xn1, v2 = xn2, v3 = xn3;
            const int tq = tp + 4;
            if (tq < T_STEPS) {
                xn0 = *reinterpret_cast<const float4*>(xrow + (size_t)tq * FD + 0);
                xn1 = *reinterpret_cast<const float4*>(xrow + (size_t)tq * FD + 4);
                xn2 = *reinterpret_cast<const float4*>(xrow + (size_t)tq * FD + 8);
                xn3 = *reinterpret_cast<const float4*>(xrow + (size_t)tq * FD + 12);
            }
            produce(tp, v0, v1, v2, v3);
        }

        // h-independent step work (o_x prescaled by 2*log2e)
        float4 P1 = *reinterpret_cast<const float4*>(xs + t * 8 + 4);
        float pc  = xs[t * 8 + pidx];
        float o_x = fmaf(P1.x, woHX[0],
                    fmaf(P1.y, woHX[1], fmaf(P1.z, woHX[2],
                    fmaf(P1.w, woHX[3], boHX))));

        u64 aA0 = 0ull, aA1 = 0ull, aB0 = 0ull, aB1 = 0ull;
        aA0 = fma2(q0.x, wA[0], aA0); aA1 = fma2(q0.y, wA[1], aA1);
        aB0 = fma2(q0.x, wB[0], aB0); aB1 = fma2(q0.y, wB[1], aB1);
        aA0 = fma2(q1.x, wA[2], aA0); aA1 = fma2(q1.y, wA[3], aA1);
        aB0 = fma2(q1.x, wB[2], aB0); aB1 = fma2(q1.y, wB[3], aB1);
        aA0 = fma2(q2.x, wA[4], aA0); aA1 = fma2(q2.y, wA[5], aA1);
        aB0 = fma2(q2.x, wB[4], aB0); aB1 = fma2(q2.y, wB[5], aB1);
        aA0 = fma2(q3.x, wA[6], aA0); aA1 = fma2(q3.y, wA[7], aA1);
        aB0 = fma2(q3.x, wB[6], aB0); aB1 = fma2(q3.y, wB[7], aB1);

        aA0 = add2(aA0, aA1);
        aB0 = add2(aB0, aB1);
        float alo, ahi, blo, bhi;
        unpack2(aA0, alo, ahi);
        unpack2(aB0, blo, bhi);
        float sA = alo + ahi;
        float sB = blo + bhi;

        // 3-shuffle value-splitting reduction over the 8-lane group
        float send = (sub & 4) ? sA : sB;
        float recv = __shfl_xor_sync(0xffffffffu, send, 4);
        float s = ((sub & 4) ? sB : sA) + recv;
        s += __shfl_xor_sync(0xffffffffu, s, 2);
        s += __shfl_xor_sync(0xffffffffu, s, 1);

        // one warp-wide cosine computes this warp's 12 gate cosines
        float arg = s + cadd + (use_p ? pc : 0.0f);
        float cv  = __cosf(arg);
        if (slot >= 0) cbuf[slot] = cv;
        __syncwarp();

        float4 CR = *reinterpret_cast<const float4*>(cbuf + 0);
        float4 CZ = *reinterpret_cast<const float4*>(cbuf + 4);
        float4 CH = *reinterpret_cast<const float4*>(cbuf + 8);

        // z-expectations after CNOT ring: (C1C2C3, C0C1, C0C1C2, C0C1C2C3)
        float rm = CR.y * CR.z;
        float rA = CR.x * CR.y, rB = CR.x * rm;
        float o_r = fmaf(rm * CR.w, woRZ[0],
                    fmaf(rA, woRZ[1], fmaf(rB, woRZ[2],
                    fmaf(rB * CR.w, woRZ[3], boRZ))));
        float Er = ex2f(-o_r);

        float hm = CH.y * CH.z;
        float hA = CH.x * CH.y, hB = CH.x * hm;
        float o_h = fmaf(hm * CH.w, woHX[0],
                    fmaf(hA, woHX[1], fmaf(hB, woHX[2],
                    fmaf(hB * CH.w, woHX[3], boHX))));

        float zm = CZ.y * CZ.z;
        float zA = CZ.x * CZ.y, zB = CZ.x * zm;
        float o_z = fmaf(zm * CZ.w, woRZ[0],
                    fmaf(zA, woRZ[1], fmaf(zB, woRZ[2],
                    fmaf(zB * CZ.w, woRZ[3], boRZ))));
        float Ez = ex2f(-o_z);

        // u2 = 2*log2e*(o_x + o_h*r), r = sigmoid(o_r)
        float r  = rcpf(1.0f + Er);
        float u2 = fmaf(o_h, r, o_x);
        float Eu = ex2f(-u2);

        // h' = (Ez(1-Eu) + h(1+Eu)) / ((1+Eu)(1+Ez))
        float t2  = 1.0f + Eu;
        float num = fmaf(Ez, 1.0f - Eu, hj * t2);
        float den = t2 * (1.0f + Ez);
        hj = num * rcpf(den);

        h_sh[(t + 1) & 1][j] = hj;        // publish to other lanes

        __syncthreads();
        prev = hj;
    }

    orow[(size_t)(T_STEPS - 1) * HD] = prev;
    // h_last
    out[(size_t)NB * T_STEPS * HD + b * HD + j] = hj;
}

extern "C" void kernel_launch(void* const* d_in, const int* in_sizes, int n_in,
                              void* d_out, int out_size) {
    const float* x     = (const float*)d_in[0];
    const float* W_in  = (const float*)d_in[1];
    const float* b_in  = (const float*)d_in[2];
    const float* W_x   = (const float*)d_in[3];
    const float* b_x   = (const float*)d_in[4];
    const float* W_h   = (const float*)d_in[5];
    const float* b_h   = (const float*)d_in[6];
    const float* W_out = (const float*)d_in[7];
    const float* b_out = (const float*)d_in[8];
    const float* vqcw  = (const float*)d_in[9];
    float* out = (float*)d_out;

    qgru_fused<<<NB, HD>>>(x, W_in, b_in, W_x, b_x, W_h, b_h,
                           W_out, b_out, vqcw, out);
}

// round 10
// speedup vs baseline: 2.4651x; 2.4651x over previous
#include <cuda_runtime.h>
#include <math.h>

#define T_STEPS 1024
#define NB 128
#define FD 128
#define HD 128

// Scratch: 8 precomputed floats per (b,t):
//  [0:4) = x_t @ W_in_x^T + b_in   (x-part of y)
//  [4:8) = vqc(x_t @ W_x^T + b_x, vqc_w[2])  (fully h-independent)
__device__ float g_xpre[NB * T_STEPS * 8];

typedef unsigned long long u64;

__device__ __forceinline__ u64 pack2(float lo, float hi) {
    u64 r;
    asm("mov.b64 %0, {%1, %2};" : "=l"(r) : "f"(lo), "f"(hi));
    return r;
}
__device__ __forceinline__ float ex2f(float x) {
    float r;
    asm("ex2.approx.f32 %0, %1;" : "=f"(r) : "f"(x));
    return r;
}
__device__ __forceinline__ float rcpf(float x) {
    float r;
    asm("rcp.approx.f32 %0, %1;" : "=f"(r) : "f"(x));
    return r;
}

// ---------------------------------------------------------------------------
// Pre-pass: one warp per (b,t) row, grid-stride. Memory bound (~64MB read).
// (unchanged from R5 — proven)
// ---------------------------------------------------------------------------
__global__ void __launch_bounds__(256) qgru_prepass(
    const float* __restrict__ x,
    const float* __restrict__ W_in, const float* __restrict__ b_in,
    const float* __restrict__ W_x,  const float* __restrict__ b_x,
    const float* __restrict__ vqc_w)
{
    const int lane = threadIdx.x & 31;
    const int gw   = (blockIdx.x * blockDim.x + threadIdx.x) >> 5;
    const int nw   = (gridDim.x * blockDim.x) >> 5;

    float wt[8][4];
#pragma unroll
    for (int k = 0; k < 4; k++) {
#pragma unroll
        for (int i = 0; i < 4; i++) {
            wt[k][i]     = W_in[k * (HD + FD) + HD + lane * 4 + i];
            wt[4 + k][i] = W_x[k * FD + lane * 4 + i];
        }
    }
    float bi[8], w2[4];
#pragma unroll
    for (int k = 0; k < 4; k++) {
        bi[k]     = b_in[k];
        bi[4 + k] = b_x[k];
        w2[k]     = vqc_w[2 * 4 + k];
    }

    const int NROWS = NB * T_STEPS;
#pragma unroll 2
    for (int row = gw; row < NROWS; row += nw) {
        float4 xv = *reinterpret_cast<const float4*>(x + (size_t)row * FD + lane * 4);
        float s[8];
#pragma unroll
        for (int k = 0; k < 8; k++) {
            s[k] = wt[k][0] * xv.x;
            s[k] = fmaf(wt[k][1], xv.y, s[k]);
            s[k] = fmaf(wt[k][2], xv.z, s[k]);
            s[k] = fmaf(wt[k][3], xv.w, s[k]);
        }
#pragma unroll
        for (int off = 16; off; off >>= 1) {
#pragma unroll
            for (int k = 0; k < 8; k++)
                s[k] += __shfl_xor_sync(0xffffffffu, s[k], off);
        }
        if (lane == 0) {
            float c0 = __cosf(s[4] + bi[4] + w2[0]);
            float c1 = __cosf(s[5] + bi[5] + w2[1]);
            float c2 = __cosf(s[6] + bi[6] + w2[2]);
            float c3 = __cosf(s[7] + bi[7] + w2[3]);
            float z1 = c0 * c1;
            float z2 = z1 * c2;
            float4 o0 = make_float4(s[0] + bi[0], s[1] + bi[1],
                                    s[2] + bi[2], s[3] + bi[3]);
            float4 o1 = make_float4(c1 * c2 * c3, z1, z2, z2 * c3);
            float4* op = reinterpret_cast<float4*>(g_xpre + (size_t)row * 8);
            op[0] = o0;
            op[1] = o1;
        }
    }
}

// ---------------------------------------------------------------------------
// Sequential recurrence: 1 CTA per batch row, 128 threads; thread j owns
// h_j IN A REGISTER (no h smem round-trip). Warp w's dot slice is exactly
// its own lanes' h values: 8 FMUL + 9-shuffle value-split butterfly gives
// lane quad 4k the warp-partial sum k. Only 32 floats (psum[8][4]) cross
// the per-step barrier. Post-barrier: one float4 read per lane -> total,
// one warp-wide MUFU.COS -> 12 cosines via per-warp smem slot, ex2-folded
// merged-division GRU update.
// ---------------------------------------------------------------------------
__global__ void __launch_bounds__(128, 1) qgru_seq(
    const float* __restrict__ W_in, const float* __restrict__ W_h,
    const float* __restrict__ b_h,
    const float* __restrict__ W_out, const float* __restrict__ b_out,
    const float* __restrict__ vqc_w,
    float* __restrict__ out)
{
    const int b    = blockIdx.x;
    const int j    = threadIdx.x;
    const int lane = j & 31;
    const int w    = j >> 5;
    const int k    = lane >> 2;   // owned sum index after butterfly
    const int q    = lane & 3;

    __shared__ __align__(16) float xs[T_STEPS * 8];   // 32 KB staged xpre row
    __shared__ __align__(16) float psum[2][8][4];     // [buf][sum][warp]
    __shared__ __align__(16) float cos_sh[4][16];     // slots 0..11 used

    // ---- stage this row's xpre into smem
    {
        const float4* src = reinterpret_cast<const float4*>(
            g_xpre + (size_t)b * T_STEPS * 8);
        float4* dst = reinterpret_cast<float4*>(xs);
        float4 tmp[16];
#pragma unroll
        for (int i = 0; i < 16; i++) tmp[i] = src[j + 128 * i];
#pragma unroll
        for (int i = 0; i < 16; i++) dst[j + 128 * i] = tmp[i];
    }

    // ---- dot weights: wk[kk] = row_kk[j]  (thread j's h column)
    float wk[8];
#pragma unroll
    for (int kk = 0; kk < 8; kk++) {
        const float* row = (kk < 4) ? (W_in + kk * (HD + FD))
                                    : (W_h + (kk - 4) * HD);
        wk[kk] = row[j];
    }

    // W_out prescaled: RZ by log2e (exp(-o)), HX by 2*log2e (exp(-2u))
    const float L2E = 1.4426950408889634f;
    float woRZ[4], woHX[4];
#pragma unroll
    for (int kk = 0; kk < 4; kk++) {
        float wv = W_out[j * 4 + kk];
        woRZ[kk] = wv * L2E;
        woHX[kk] = wv * (2.0f * L2E);
    }
    const float bof  = b_out[j];
    const float boRZ = bof * L2E;
    const float boHX = bof * (2.0f * L2E);

    // ---- cosine role (loop-invariant): quad k, member q
    int slot = -1;
    float cadd = 0.0f;
    if (k < 4) {
        if (q == 0)      { slot = k;     cadd = vqc_w[k]; }
        else if (q == 1) { slot = 4 + k; cadd = vqc_w[4 + k]; }
    } else {
        int kk = k - 4;
        if (q == 0)      { slot = 8 + kk; cadd = vqc_w[12 + kk] + b_h[kk]; }
    }
    const bool use_p = (k < 4);

    const int hi = (lane >> 4) & 1;
    const int h3 = (lane >> 3) & 1;
    const int h2 = (lane >> 2) & 1;

    float hj = 0.0f;                 // h_j lives here; never leaves registers

    // c_last = zeros
    out[(size_t)NB * T_STEPS * HD + (size_t)NB * HD + b * HD + j] = 0.0f;

    float* __restrict__ orow = out + (size_t)b * T_STEPS * HD + j;
    float* cbuf = cos_sh[w];

    __syncthreads();   // xs staged

#pragma unroll 1
    for (int t = 0; t < T_STEPS; t++) {
        // ---- pre-barrier: warp-partial dots over this warp's own h slice
        float v[8];
#pragma unroll
        for (int kk = 0; kk < 8; kk++) v[kk] = wk[kk] * hj;

        // 5-round value-splitting butterfly (9 shuffles): lane quad 4k
        // ends with this warp's partial sum k (replicated in the quad)
        float u4_0, u4_1, u4_2, u4_3;
        {
            float s0 = hi ? v[0] : v[4];
            float s1 = hi ? v[1] : v[5];
            float s2 = hi ? v[2] : v[6];
            float s3 = hi ? v[3] : v[7];
            float r0 = __shfl_xor_sync(0xffffffffu, s0, 16);
            float r1 = __shfl_xor_sync(0xffffffffu, s1, 16);
            float r2 = __shfl_xor_sync(0xffffffffu, s2, 16);
            float r3 = __shfl_xor_sync(0xffffffffu, s3, 16);
            u4_0 = (hi ? v[4] : v[0]) + r0;
            u4_1 = (hi ? v[5] : v[1]) + r1;
            u4_2 = (hi ? v[6] : v[2]) + r2;
            u4_3 = (hi ? v[7] : v[3]) + r3;
        }
        float u2_0, u2_1;
        {
            float s0 = h3 ? u4_0 : u4_2;
            float s1 = h3 ? u4_1 : u4_3;
            float r0 = __shfl_xor_sync(0xffffffffu, s0, 8);
            float r1 = __shfl_xor_sync(0xffffffffu, s1, 8);
            u2_0 = (h3 ? u4_2 : u4_0) + r0;
            u2_1 = (h3 ? u4_3 : u4_1) + r1;
        }
        float s;
        {
            float s0 = h2 ? u2_0 : u2_1;
            float r0 = __shfl_xor_sync(0xffffffffu, s0, 4);
            s = (h2 ? u2_1 : u2_0) + r0;
        }
        s += __shfl_xor_sync(0xffffffffu, s, 2);
        s += __shfl_xor_sync(0xffffffffu, s, 1);

        if (q == 0) psum[t & 1][k][w] = s;

        // psum-independent work overlapping the barrier region
        float4 P1 = *reinterpret_cast<const float4*>(xs + t * 8 + 4);
        float pc  = xs[t * 8 + (k & 3)];
        float o_x = fmaf(P1.x, woHX[0],
                    fmaf(P1.y, woHX[1], fmaf(P1.z, woHX[2],
                    fmaf(P1.w, woHX[3], boHX))));

        __syncthreads();

        // ---- post-barrier: total for owned sum k (4 warp partials)
        float4 p4 = *reinterpret_cast<const float4*>(psum[t & 1][k]);
        float tot = (p4.x + p4.y) + (p4.z + p4.w);

        // one warp-wide cosine computes this warp's 12 gate cosines
        float arg = tot + cadd + (use_p ? pc : 0.0f);
        float cv  = __cosf(arg);
        if (slot >= 0) cbuf[slot] = cv;
        __syncwarp();

        float4 CR = *reinterpret_cast<const float4*>(cbuf + 0);
        float4 CZ = *reinterpret_cast<const float4*>(cbuf + 4);
        float4 CH = *reinterpret_cast<const float4*>(cbuf + 8);

        // z-expectations after CNOT ring: (C1C2C3, C0C1, C0C1C2, C0C1C2C3)
        float rm = CR.y * CR.z;
        float rA = CR.x * CR.y, rB = CR.x * rm;
        float o_r = fmaf(rm * CR.w, woRZ[0],
                    fmaf(rA, woRZ[1], fmaf(rB, woRZ[2],
                    fmaf(rB * CR.w, woRZ[3], boRZ))));
        float Er = ex2f(-o_r);

        float hm = CH.y * CH.z;
        float hA = CH.x * CH.y, hB = CH.x * hm;
        float o_h = fmaf(hm * CH.w, woHX[0],
                    fmaf(hA, woHX[1], fmaf(hB, woHX[2],
                    fmaf(hB * CH.w, woHX[3], boHX))));

        float zm = CZ.y * CZ.z;
        float zA = CZ.x * CZ.y, zB = CZ.x * zm;
        float o_z = fmaf(zm * CZ.w, woRZ[0],
                    fmaf(zA, woRZ[1], fmaf(zB, woRZ[2],
                    fmaf(zB * CZ.w, woRZ[3], boRZ))));
        float Ez = ex2f(-o_z);

        // u2 = 2*log2e*(o_x + o_h*r), r = sigmoid(o_r)
        float r  = rcpf(1.0f + Er);
        float u2 = fmaf(o_h, r, o_x);
        float Eu = ex2f(-u2);

        // h' = (Ez(1-Eu) + h(1+Eu)) / ((1+Eu)(1+Ez))
        float t2  = 1.0f + Eu;
        float num = fmaf(Ez, 1.0f - Eu, hj * t2);
        float den = t2 * (1.0f + Ez);
        hj = num * rcpf(den);

        orow[(size_t)t * HD] = hj;      // hidden_seq[b, t, j] (off-chain STG)
    }

    // h_last
    out[(size_t)NB * T_STEPS * HD + b * HD + j] = hj;
}

extern "C" void kernel_launch(void* const* d_in, const int* in_sizes, int n_in,
                              void* d_out, int out_size) {
    const float* x     = (const float*)d_in[0];
    const float* W_in  = (const float*)d_in[1];
    const float* b_in  = (const float*)d_in[2];
    const float* W_x   = (const float*)d_in[3];
    const float* b_x   = (const float*)d_in[4];
    const float* W_h   = (const float*)d_in[5];
    const float* b_h   = (const float*)d_in[6];
    const float* W_out = (const float*)d_in[7];
    const float* b_out = (const float*)d_in[8];
    const float* vqcw  = (const float*)d_in[9];
    float* out = (float*)d_out;

    qgru_prepass<<<1184, 256>>>(x, W_in, b_in, W_x, b_x, vqcw);
    qgru_seq<<<NB, HD>>>(W_in, W_h, b_h, W_out, b_out, vqcw, out);
}

// round 11
// speedup vs baseline: 2.5707x; 1.0429x over previous
#include <cuda_runtime.h>
#include <math.h>

#define T_STEPS 1024
#define NB 128
#define FD 128
#define HD 128

// Scratch: 8 precomputed floats per (b,t):
//  [0:4) = x_t @ W_in_x^T + b_in   (x-part of y)
//  [4:8) = vqc(x_t @ W_x^T + b_x, vqc_w[2])  (fully h-independent)
__device__ float g_xpre[NB * T_STEPS * 8];

typedef unsigned long long u64;

__device__ __forceinline__ u64 add2(u64 a, u64 b) {
    u64 r;
    asm("add.rn.f32x2 %0, %1, %2;" : "=l"(r) : "l"(a), "l"(b));
    return r;
}
__device__ __forceinline__ void unpack2(u64 v, float& lo, float& hi) {
    asm("mov.b64 {%0, %1}, %2;" : "=f"(lo), "=f"(hi) : "l"(v));
}
__device__ __forceinline__ float ex2f(float x) {
    float r;
    asm("ex2.approx.f32 %0, %1;" : "=f"(r) : "f"(x));
    return r;
}
__device__ __forceinline__ float rcpf(float x) {
    float r;
    asm("rcp.approx.f32 %0, %1;" : "=f"(r) : "f"(x));
    return r;
}

// ---------------------------------------------------------------------------
// Pre-pass: one warp per (b,t) row, grid-stride. Memory bound (~64MB read).
// (unchanged — proven)
// ---------------------------------------------------------------------------
__global__ void __launch_bounds__(256) qgru_prepass(
    const float* __restrict__ x,
    const float* __restrict__ W_in, const float* __restrict__ b_in,
    const float* __restrict__ W_x,  const float* __restrict__ b_x,
    const float* __restrict__ vqc_w)
{
    const int lane = threadIdx.x & 31;
    const int gw   = (blockIdx.x * blockDim.x + threadIdx.x) >> 5;
    const int nw   = (gridDim.x * blockDim.x) >> 5;

    float wt[8][4];
#pragma unroll
    for (int k = 0; k < 4; k++) {
#pragma unroll
        for (int i = 0; i < 4; i++) {
            wt[k][i]     = W_in[k * (HD + FD) + HD + lane * 4 + i];
            wt[4 + k][i] = W_x[k * FD + lane * 4 + i];
        }
    }
    float bi[8], w2[4];
#pragma unroll
    for (int k = 0; k < 4; k++) {
        bi[k]     = b_in[k];
        bi[4 + k] = b_x[k];
        w2[k]     = vqc_w[2 * 4 + k];
    }

    const int NROWS = NB * T_STEPS;
#pragma unroll 2
    for (int row = gw; row < NROWS; row += nw) {
        float4 xv = *reinterpret_cast<const float4*>(x + (size_t)row * FD + lane * 4);
        float s[8];
#pragma unroll
        for (int k = 0; k < 8; k++) {
            s[k] = wt[k][0] * xv.x;
            s[k] = fmaf(wt[k][1], xv.y, s[k]);
            s[k] = fmaf(wt[k][2], xv.z, s[k]);
            s[k] = fmaf(wt[k][3], xv.w, s[k]);
        }
#pragma unroll
        for (int off = 16; off; off >>= 1) {
#pragma unroll
            for (int k = 0; k < 8; k++)
                s[k] += __shfl_xor_sync(0xffffffffu, s[k], off);
        }
        if (lane == 0) {
            float c0 = __cosf(s[4] + bi[4] + w2[0]);
            float c1 = __cosf(s[5] + bi[5] + w2[1]);
            float c2 = __cosf(s[6] + bi[6] + w2[2]);
            float c3 = __cosf(s[7] + bi[7] + w2[3]);
            float z1 = c0 * c1;
            float z2 = z1 * c2;
            float4 o0 = make_float4(s[0] + bi[0], s[1] + bi[1],
                                    s[2] + bi[2], s[3] + bi[3]);
            float4 o1 = make_float4(c1 * c2 * c3, z1, z2, z2 * c3);
            float4* op = reinterpret_cast<float4*>(g_xpre + (size_t)row * 8);
            op[0] = o0;
            op[1] = o1;
        }
    }
}

// ---------------------------------------------------------------------------
// Sequential recurrence: 1 CTA per batch row, 128 threads; thread j owns
// h_j in a register. Per step:
//  - 8 FMUL partials, 3-round (5-shuffle) value-split butterfly: every lane
//    ends with one partial (sum k=lane>>2, partial p=lane&3 over 8 lanes)
//  - all 32 lanes STS into padded psum rows (stride 20 -> conflict-free)
//  - barrier; each lane reads its sum's 16 partials (4x LDS.128,
//    conflict-free) and reduces with packed add2 tree
//  - one warp-wide MUFU.COS -> 12 gate cosines via 12 direct shfl.idx
//    (producers at lanes 4k, 4k+1, 16+4i); no smem round-trip
//  - ex2-folded merged-division GRU update
// ---------------------------------------------------------------------------
__global__ void __launch_bounds__(128, 1) qgru_seq(
    const float* __restrict__ W_in, const float* __restrict__ W_h,
    const float* __restrict__ b_h,
    const float* __restrict__ W_out, const float* __restrict__ b_out,
    const float* __restrict__ vqc_w,
    float* __restrict__ out)
{
    const int b    = blockIdx.x;
    const int j    = threadIdx.x;
    const int lane = j & 31;
    const int w    = j >> 5;
    const int k    = lane >> 2;   // owned sum index after 3-round butterfly
    const int q    = lane & 3;    // partial index this lane holds

    __shared__ __align__(16) float xs[T_STEPS * 8];   // 32 KB staged xpre row
    __shared__ __align__(16) float psum[2][8 * 20];   // padded: row k at k*20

    // ---- stage this row's xpre into smem
    {
        const float4* src = reinterpret_cast<const float4*>(
            g_xpre + (size_t)b * T_STEPS * 8);
        float4* dst = reinterpret_cast<float4*>(xs);
        float4 tmp[16];
#pragma unroll
        for (int i = 0; i < 16; i++) tmp[i] = src[j + 128 * i];
#pragma unroll
        for (int i = 0; i < 16; i++) dst[j + 128 * i] = tmp[i];
    }

    // ---- dot weights: wk[kk] = row_kk[j]  (thread j's h column)
    float wk[8];
#pragma unroll
    for (int kk = 0; kk < 8; kk++) {
        const float* row = (kk < 4) ? (W_in + kk * (HD + FD))
                                    : (W_h + (kk - 4) * HD);
        wk[kk] = row[j];
    }

    // W_out prescaled: RZ by log2e (exp(-o)), HX by 2*log2e (exp(-2u))
    const float L2E = 1.4426950408889634f;
    float woRZ[4], woHX[4];
#pragma unroll
    for (int kk = 0; kk < 4; kk++) {
        float wv = W_out[j * 4 + kk];
        woRZ[kk] = wv * L2E;
        woHX[kk] = wv * (2.0f * L2E);
    }
    const float bof  = b_out[j];
    const float boRZ = bof * L2E;
    const float boHX = bof * (2.0f * L2E);

    // ---- cosine role (loop-invariant): quad k, member q
    // q==0: cr_k (k<4) or ch_{k-4} (k>=4); q==1 & k<4: cz_k; else idle (arg
    // still computed, result unused).
    float cadd = 0.0f;
    if (k < 4) {
        if (q == 0)      cadd = vqc_w[k];
        else if (q == 1) cadd = vqc_w[4 + k];
    } else if (q == 0) {
        cadd = vqc_w[12 + (k - 4)] + b_h[k - 4];
    }
    const bool use_p = (k < 4);

    const int hi = (lane >> 4) & 1;
    const int h3 = (lane >> 3) & 1;
    const int h2 = (lane >> 2) & 1;

    float hj = 0.0f;                 // h_j lives here; never leaves registers

    // c_last = zeros
    out[(size_t)NB * T_STEPS * HD + (size_t)NB * HD + b * HD + j] = 0.0f;

    float* __restrict__ orow = out + (size_t)b * T_STEPS * HD + j;
    const int pslot = k * 20 + w * 4 + q;   // this lane's psum store index

    __syncthreads();   // xs staged

#pragma unroll 1
    for (int t = 0; t < T_STEPS; t++) {
        // ---- pre-barrier: warp-partial dots over this warp's own h slice
        float v[8];
#pragma unroll
        for (int kk = 0; kk < 8; kk++) v[kk] = wk[kk] * hj;

        // 3-round value-splitting butterfly (5 shuffles): lane ends with one
        // partial: sum k=lane>>2, over the 8 lanes sharing lane&3.
        float u4_0, u4_1, u4_2, u4_3;
        {
            float s0 = hi ? v[0] : v[4];
            float s1 = hi ? v[1] : v[5];
            float s2 = hi ? v[2] : v[6];
            float s3 = hi ? v[3] : v[7];
            float r0 = __shfl_xor_sync(0xffffffffu, s0, 16);
            float r1 = __shfl_xor_sync(0xffffffffu, s1, 16);
            float r2 = __shfl_xor_sync(0xffffffffu, s2, 16);
            float r3 = __shfl_xor_sync(0xffffffffu, s3, 16);
            u4_0 = (hi ? v[4] : v[0]) + r0;
            u4_1 = (hi ? v[5] : v[1]) + r1;
            u4_2 = (hi ? v[6] : v[2]) + r2;
            u4_3 = (hi ? v[7] : v[3]) + r3;
        }
        float u2_0, u2_1;
        {
            float s0 = h3 ? u4_0 : u4_2;
            float s1 = h3 ? u4_1 : u4_3;
            float r0 = __shfl_xor_sync(0xffffffffu, s0, 8);
            float r1 = __shfl_xor_sync(0xffffffffu, s1, 8);
            u2_0 = (h3 ? u4_2 : u4_0) + r0;
            u2_1 = (h3 ? u4_3 : u4_1) + r1;
        }
        float s;
        {
            float s0 = h2 ? u2_0 : u2_1;
            float r0 = __shfl_xor_sync(0xffffffffu, s0, 4);
            s = (h2 ? u2_1 : u2_0) + r0;
        }

        psum[t & 1][pslot] = s;      // all 32 lanes store (conflict-free)

        // psum-independent work overlapping the barrier region
        float4 P1 = *reinterpret_cast<const float4*>(xs + t * 8 + 4);
        float pc  = xs[t * 8 + (k & 3)];
        float o_x = fmaf(P1.x, woHX[0],
                    fmaf(P1.y, woHX[1], fmaf(P1.z, woHX[2],
                    fmaf(P1.w, woHX[3], boHX))));

        __syncthreads();

        // ---- post-barrier: total for owned sum k (16 partials, add2 tree)
        const float* prow = psum[t & 1] + k * 20;
        ulonglong2 A = *reinterpret_cast<const ulonglong2*>(prow + 0);
        ulonglong2 B = *reinterpret_cast<const ulonglong2*>(prow + 4);
        ulonglong2 C = *reinterpret_cast<const ulonglong2*>(prow + 8);
        ulonglong2 D = *reinterpret_cast<const ulonglong2*>(prow + 12);
        u64 e0 = add2(A.x, A.y);
        u64 e1 = add2(B.x, B.y);
        u64 e2 = add2(C.x, C.y);
        u64 e3 = add2(D.x, D.y);
        e0 = add2(e0, e1);
        e2 = add2(e2, e3);
        e0 = add2(e0, e2);
        float tlo, thi;
        unpack2(e0, tlo, thi);
        float tot = tlo + thi;

        // one warp-wide cosine; 12 direct shfl.idx broadcasts (no smem)
        float arg = tot + cadd + (use_p ? pc : 0.0f);
        float cv  = __cosf(arg);

        float cr0 = __shfl_sync(0xffffffffu, cv, 0);
        float cr1 = __shfl_sync(0xffffffffu, cv, 4);
        float cr2 = __shfl_sync(0xffffffffu, cv, 8);
        float cr3 = __shfl_sync(0xffffffffu, cv, 12);
        float cz0 = __shfl_sync(0xffffffffu, cv, 1);
        float cz1 = __shfl_sync(0xffffffffu, cv, 5);
        float cz2 = __shfl_sync(0xffffffffu, cv, 9);
        float cz3 = __shfl_sync(0xffffffffu, cv, 13);
        float ch0 = __shfl_sync(0xffffffffu, cv, 16);
        float ch1 = __shfl_sync(0xffffffffu, cv, 20);
        float ch2 = __shfl_sync(0xffffffffu, cv, 24);
        float ch3 = __shfl_sync(0xffffffffu, cv, 28);

        // z-expectations after CNOT ring: (C1C2C3, C0C1, C0C1C2, C0C1C2C3)
        float rm = cr1 * cr2;
        float rA = cr0 * cr1, rB = cr0 * rm;
        float o_r = fmaf(rm * cr3, woRZ[0],
                    fmaf(rA, woRZ[1], fmaf(rB, woRZ[2],
                    fmaf(rB * cr3, woRZ[3], boRZ))));
        float Er = ex2f(-o_r);

        float hm = ch1 * ch2;
        float hA = ch0 * ch1, hB = ch0 * hm;
        float o_h = fmaf(hm * ch3, woHX[0],
                    fmaf(hA, woHX[1], fmaf(hB, woHX[2],
                    fmaf(hB * ch3, woHX[3], boHX))));

        float zm = cz1 * cz2;
        float zA = cz0 * cz1, zB = cz0 * zm;
        float o_z = fmaf(zm * cz3, woRZ[0],
                    fmaf(zA, woRZ[1], fmaf(zB, woRZ[2],
                    fmaf(zB * cz3, woRZ[3], boRZ))));
        float Ez = ex2f(-o_z);

        // u2 = 2*log2e*(o_x + o_h*r), r = sigmoid(o_r)
        float r  = rcpf(1.0f + Er);
        float u2 = fmaf(o_h, r, o_x);
        float Eu = ex2f(-u2);

        // h' = (Ez(1-Eu) + h(1+Eu)) / ((1+Eu)(1+Ez))
        float t2  = 1.0f + Eu;
        float num = fmaf(Ez, 1.0f - Eu, hj * t2);
        float den = t2 * (1.0f + Ez);
        hj = num * rcpf(den);

        orow[(size_t)t * HD] = hj;      // hidden_seq[b, t, j] (off-chain STG)
    }

    // h_last
    out[(size_t)NB * T_STEPS * HD + b * HD + j] = hj;
}

extern "C" void kernel_launch(void* const* d_in, const int* in_sizes, int n_in,
                              void* d_out, int out_size) {
    const float* x     = (const float*)d_in[0];
    const float* W_in  = (const float*)d_in[1];
    const float* b_in  = (const float*)d_in[2];
    const float* W_x   = (const float*)d_in[3];
    const float* b_x   = (const float*)d_in[4];
    const float* W_h   = (const float*)d_in[5];
    const float* b_h   = (const float*)d_in[6];
    const float* W_out = (const float*)d_in[7];
    const float* b_out = (const float*)d_in[8];
    const float* vqcw  = (const float*)d_in[9];
    float* out = (float*)d_out;

    qgru_prepass<<<1184, 256>>>(x, W_in, b_in, W_x, b_x, vqcw);
    qgru_seq<<<NB, HD>>>(W_in, W_h, b_h, W_out, b_out, vqcw, out);
}